// round 6
// baseline (speedup 1.0000x reference)
#include <cuda_runtime.h>
#include <math.h>
#include <stdint.h>

#define BB 2
#define TT 2048
#define CC 512
#define NB 4
#define QN (NB*CC)   // 2048
#define HALF (CC/2)  // 256

// Scratch (no cudaMalloc allowed)
__device__ float g_Q[BB*TT*QN];
__device__ float g_K[BB*TT*CC];
__device__ float g_V[BB*TT*QN];
__device__ float g_Y[BB*TT*CC];

__device__ __forceinline__ uint32_t f2tf32(float f) {
    uint32_t r;
    asm("cvt.rna.tf32.f32 %0, %1;" : "=r"(r) : "f"(f));
    return r;
}
__device__ __forceinline__ void mma_tf32(
    float& c0, float& c1, float& c2, float& c3,
    uint32_t a0, uint32_t a1, uint32_t a2, uint32_t a3,
    uint32_t b0, uint32_t b1)
{
    asm("mma.sync.aligned.m16n8k8.row.col.f32.tf32.tf32.f32 "
        "{%0,%1,%2,%3}, {%4,%5,%6,%7}, {%8,%9}, {%0,%1,%2,%3};"
        : "+f"(c0), "+f"(c1), "+f"(c2), "+f"(c3)
        : "r"(a0), "r"(a1), "r"(a2), "r"(a3), "r"(b0), "r"(b1));
}

// ---------------------------------------------------------------------------
// Tensor-core GEMM (tf32 mma.sync): Out[M,N] = A[M,K] @ W[K,N], fp32 I/O.
// SPLIT=1: error-corrected split-tf32 (hi/lo, 3 MMAs) -> ~fp32 accuracy.
// CTA 128x128, BK=16, 8 warps (2Mx4N), warp tile 64x32.
// smem layout [k%4][row][swz(k/4)] ; pair-swizzle cuts LDS conflicts to 2-way.
// Optional RoPE + scale epilogue in fp32.
// ---------------------------------------------------------------------------
template<int DO_ROPE, int SPLIT>
__global__ void __launch_bounds__(256) gemm_tc(
    const float* __restrict__ A, const float* __restrict__ W, float* __restrict__ Out,
    int M, int N, int K,
    const float* __restrict__ cosT, const float* __restrict__ sinT, float scale)
{
    constexpr int BM = 128, BN = 128, BK = 16;
    __shared__ alignas(16) uint32_t Ah[4][BM][4];
    __shared__ alignas(16) uint32_t Al[4][BM][4];
    __shared__ alignas(16) uint32_t Wh[4][BN][4];
    __shared__ alignas(16) uint32_t Wl[4][BN][4];

    const int tid    = threadIdx.x;
    const int warpid = tid >> 5;
    const int lane   = tid & 31;
    const int g      = lane >> 2;   // groupID 0..7
    const int tig    = lane & 3;    // thread-in-group 0..3

    const int wm = (warpid & 1) * 64;
    const int wn = (warpid >> 1) * 32;
    const int rowBase = blockIdx.y * BM;
    const int colBase = blockIdx.x * BN;

    float acc[4][4][4];
#pragma unroll
    for (int mt = 0; mt < 4; mt++)
#pragma unroll
        for (int nt = 0; nt < 4; nt++)
#pragma unroll
            for (int c = 0; c < 4; c++) acc[mt][nt][c] = 0.f;

    for (int k0 = 0; k0 < K; k0 += BK) {
        // --- A tile (128 x 16): element k -> pl=k&3, ix=k>>2 (pair-swizzled) ---
#pragma unroll
        for (int i = 0; i < 2; i++) {
            int slot = tid + i * 256;       // 0..511
            int r    = slot >> 2;           // 0..127
            int ixb  = slot & 3;            // k/4 index
            const float4 v = *(const float4*)(A + (size_t)(rowBase + r) * K + k0 + ixb * 4);
            float vv[4] = {v.x, v.y, v.z, v.w};
            int jp = ixb >> 1, wbit = ixb & 1;
#pragma unroll
            for (int e = 0; e < 4; e++) {   // pl = e
                int ixs = (((jp ^ (e & 1)) << 1) | wbit);
                uint32_t h = f2tf32(vv[e]);
                Ah[e][r][ixs] = h;
                if (SPLIT) Al[e][r][ixs] = f2tf32(vv[e] - __uint_as_float(h));
            }
        }
        // --- W tile (16 x 128): element (k=kr, n) -> pl=kr&3, ix=kr>>2 ---
#pragma unroll
        for (int i = 0; i < 2; i++) {
            int slot = tid + i * 256;       // 0..511
            int kr   = slot >> 5;           // 0..15
            int nc4  = slot & 31;           // 0..31
            const float4 v = *(const float4*)(W + (size_t)(k0 + kr) * N + colBase + nc4 * 4);
            float vv[4] = {v.x, v.y, v.z, v.w};
            int pl = kr & 3, ix = kr >> 2;
            int ixs = ((((ix >> 1) ^ (pl & 1)) << 1) | (ix & 1));
#pragma unroll
            for (int e = 0; e < 4; e++) {
                uint32_t h = f2tf32(vv[e]);
                Wh[pl][nc4 * 4 + e][ixs] = h;
                if (SPLIT) Wl[pl][nc4 * 4 + e][ixs] = f2tf32(vv[e] - __uint_as_float(h));
            }
        }
        __syncthreads();

#pragma unroll
        for (int j = 0; j < 2; j++) {       // k8 substep
            const int ja = 2 * (j ^ (tig & 1));   // swizzled pair slot for pl=tig
            uint32_t ah[4][4], al[4][4];
#pragma unroll
            for (int mt = 0; mt < 4; mt++) {
                int rl = wm + mt * 16 + g, rh = rl + 8;
                uint2 h0 = *(uint2*)&Ah[tig][rl][ja];
                uint2 h1 = *(uint2*)&Ah[tig][rh][ja];
                ah[mt][0] = h0.x; ah[mt][2] = h0.y;
                ah[mt][1] = h1.x; ah[mt][3] = h1.y;
                if (SPLIT) {
                    uint2 l0 = *(uint2*)&Al[tig][rl][ja];
                    uint2 l1 = *(uint2*)&Al[tig][rh][ja];
                    al[mt][0] = l0.x; al[mt][2] = l0.y;
                    al[mt][1] = l1.x; al[mt][3] = l1.y;
                }
            }
#pragma unroll
            for (int nt = 0; nt < 4; nt++) {
                int cn = wn + nt * 8 + g;
                uint2 bh = *(uint2*)&Wh[tig][cn][ja];
#pragma unroll
                for (int mt = 0; mt < 4; mt++)
                    mma_tf32(acc[mt][nt][0], acc[mt][nt][1], acc[mt][nt][2], acc[mt][nt][3],
                             ah[mt][0], ah[mt][1], ah[mt][2], ah[mt][3], bh.x, bh.y);
                if (SPLIT) {
                    uint2 bl = *(uint2*)&Wl[tig][cn][ja];
#pragma unroll
                    for (int mt = 0; mt < 4; mt++) {
                        mma_tf32(acc[mt][nt][0], acc[mt][nt][1], acc[mt][nt][2], acc[mt][nt][3],
                                 ah[mt][0], ah[mt][1], ah[mt][2], ah[mt][3], bl.x, bl.y);
                        mma_tf32(acc[mt][nt][0], acc[mt][nt][1], acc[mt][nt][2], acc[mt][nt][3],
                                 al[mt][0], al[mt][1], al[mt][2], al[mt][3], bh.x, bh.y);
                    }
                }
            }
        }
        __syncthreads();
    }

    // --- Epilogue: optional RoPE on adjacent (even,odd) column pairs ---
#pragma unroll
    for (int mt = 0; mt < 4; mt++) {
        int rowlo = rowBase + wm + mt * 16 + g;
        int rowhi = rowlo + 8;
#pragma unroll
        for (int nt = 0; nt < 4; nt++) {
            int gc = colBase + wn + nt * 8 + 2 * tig;
            float e0 = acc[mt][nt][0], o0 = acc[mt][nt][1];
            float e1 = acc[mt][nt][2], o1 = acc[mt][nt][3];
            if (DO_ROPE) {
                int i0 = (gc & (CC - 1)) >> 1;
                int tlo = rowlo & (TT - 1), thi = rowhi & (TT - 1);
                float cl = cosT[tlo * HALF + i0], sl = sinT[tlo * HALF + i0];
                float ch = cosT[thi * HALF + i0], sh = sinT[thi * HALF + i0];
                float r0 = e0 * cl - o0 * sl, r1 = e0 * sl + o0 * cl;
                float r2 = e1 * ch - o1 * sh, r3 = e1 * sh + o1 * ch;
                e0 = r0; o0 = r1; e1 = r2; o1 = r3;
            }
            *(float2*)(Out + (size_t)rowlo * N + gc) = make_float2(e0 * scale, o0 * scale);
            *(float2*)(Out + (size_t)rowhi * N + gc) = make_float2(e1 * scale, o1 * scale);
        }
    }
}

// ---------------------------------------------------------------------------
// Fused routed attention (R1 version, known-good).
// ---------------------------------------------------------------------------
__global__ void __launch_bounds__(256) attn_kernel(
    const float* __restrict__ Q, const float* __restrict__ K,
    const float* __restrict__ V, float* __restrict__ Y)
{
    constexpr int SBLK = 16;
    __shared__ float4 ks[SBLK][CC / 4];   // 32KB

    const int tid  = threadIdx.x;
    const int w    = tid >> 5;
    const int lane = tid & 31;
    const int r    = blockIdx.x * 8 + w;
    const int t    = r & (TT - 1);
    const int tmax = (blockIdx.x * 8 + 7) & (TT - 1);

    float4 q[NB][4];
    const float* qp = Q + (size_t)r * QN;
#pragma unroll
    for (int n = 0; n < NB; n++)
#pragma unroll
        for (int jj = 0; jj < 4; jj++)
            q[n][jj] = *(const float4*)(qp + n * CC + jj * 128 + lane * 4);

    float4 acc[4];
#pragma unroll
    for (int jj = 0; jj < 4; jj++) acc[jj] = make_float4(0.f, 0.f, 0.f, 0.f);
    float m = -1e30f, l = 0.f;

    const float* kb = K + (size_t)(r - t) * CC;
    const float* vb = V + (size_t)(r - t) * QN;

    for (int s0 = 0; s0 <= tmax; s0 += SBLK) {
#pragma unroll
        for (int i = 0; i < 8; i++) {
            int slot = tid + i * 256;
            int si = slot >> 7, cj = slot & 127;
            ks[si][cj] = *(const float4*)(kb + (size_t)(s0 + si) * CC + cj * 4);
        }
        __syncthreads();

        int send = t - s0; if (send > SBLK - 1) send = SBLK - 1;
        for (int si = 0; si <= send; si++) {
            float4 k4[4];
#pragma unroll
            for (int jj = 0; jj < 4; jj++) k4[jj] = ks[si][jj * 32 + lane];

            float d[NB];
#pragma unroll
            for (int n = 0; n < NB; n++) {
                float s = 0.f;
#pragma unroll
                for (int jj = 0; jj < 4; jj++) {
                    s += q[n][jj].x * k4[jj].x;
                    s += q[n][jj].y * k4[jj].y;
                    s += q[n][jj].z * k4[jj].z;
                    s += q[n][jj].w * k4[jj].w;
                }
                d[n] = s;
            }
#pragma unroll
            for (int off = 16; off > 0; off >>= 1) {
#pragma unroll
                for (int n = 0; n < NB; n++)
                    d[n] += __shfl_xor_sync(0xffffffffu, d[n], off);
            }

            float smax = d[0]; int nsel = 0;
            if (d[1] > smax) { smax = d[1]; nsel = 1; }
            if (d[2] > smax) { smax = d[2]; nsel = 2; }
            if (d[3] > smax) { smax = d[3]; nsel = 3; }

            float mnew  = fmaxf(m, smax);
            float alpha = __expf(m - mnew);
            float p     = __expf(smax - mnew);
            l = l * alpha + p;

            const float4* vr = (const float4*)(vb + (size_t)(s0 + si) * QN + (size_t)nsel * CC);
#pragma unroll
            for (int jj = 0; jj < 4; jj++) {
                float4 vv = vr[jj * 32 + lane];
                acc[jj].x = acc[jj].x * alpha + p * vv.x;
                acc[jj].y = acc[jj].y * alpha + p * vv.y;
                acc[jj].z = acc[jj].z * alpha + p * vv.z;
                acc[jj].w = acc[jj].w * alpha + p * vv.w;
            }
            m = mnew;
        }
        __syncthreads();
    }

    float inv = 1.f / l;
    float* yp = Y + (size_t)r * CC;
#pragma unroll
    for (int jj = 0; jj < 4; jj++) {
        float4 o = make_float4(acc[jj].x * inv, acc[jj].y * inv,
                               acc[jj].z * inv, acc[jj].w * inv);
        *(float4*)(yp + jj * 128 + lane * 4) = o;
    }
}

// ---------------------------------------------------------------------------
extern "C" void kernel_launch(void* const* d_in, const int* in_sizes, int n_in,
                              void* d_out, int out_size)
{
    const float* a    = (const float*)d_in[0];
    const float* x    = (const float*)d_in[1];
    const float* Wq   = (const float*)d_in[2];
    const float* Wk   = (const float*)d_in[3];
    const float* Wv   = (const float*)d_in[4];
    const float* Wo   = (const float*)d_in[5];
    const float* cosT = (const float*)d_in[6];
    const float* sinT = (const float*)d_in[7];
    float* out = (float*)d_out;

    float* Qb; cudaGetSymbolAddress((void**)&Qb, g_Q);
    float* Kb; cudaGetSymbolAddress((void**)&Kb, g_K);
    float* Vb; cudaGetSymbolAddress((void**)&Vb, g_V);
    float* Yb; cudaGetSymbolAddress((void**)&Yb, g_Y);

    const int M = BB * TT;
    const float qscale = 0.04419417382415922f;  // 1/sqrt(512)

    dim3 thr(256);
    // Q,K feed the routing argmax -> split-tf32 (fp32-accurate)
    gemm_tc<1,1><<<dim3(QN / 128, M / 128), thr>>>(a, Wq, Qb, M, QN, CC, cosT, sinT, qscale);
    gemm_tc<1,1><<<dim3(CC / 128, M / 128), thr>>>(x, Wk, Kb, M, CC, CC, cosT, sinT, 1.0f);
    // V, Wo are linear in the output -> plain tf32 is accurate enough
    gemm_tc<0,0><<<dim3(QN / 128, M / 128), thr>>>(a, Wv, Vb, M, QN, CC, nullptr, nullptr, 1.0f);
    attn_kernel<<<M / 8, thr>>>(Qb, Kb, Vb, Yb);
    gemm_tc<0,0><<<dim3(CC / 128, M / 128), thr>>>(Yb, Wo, out, M, CC, CC, nullptr, nullptr, 1.0f);
}